// round 1
// baseline (speedup 1.0000x reference)
#include <cuda_runtime.h>

// Problem constants (fixed shapes per reference)
#define NNODES 50000
#define NEDGES 800000
#define ETOT   (NNODES + NEDGES)   // edges + self loops
#define FIN    256
#define HIDTOT 256                 // HEADS*HID
#define NHEADS 4
#define NCLS   32

// ---------------- scratch (device globals; no allocation allowed) ----------
__device__ int   g_src[ETOT];
__device__ int   g_dst[ETOT];
__device__ int   g_csr[ETOT];
__device__ int   g_count[NNODES];
__device__ int   g_cursor[NNODES];
__device__ int   g_off[NNODES + 1];
__device__ int   g_bsum[64];
__device__ int   g_boff[64];
__device__ float g_h1[(size_t)NNODES * HIDTOT];
__device__ float g_als1[NNODES * NHEADS];
__device__ float g_ald1[NNODES * NHEADS];
__device__ float g_h2in[(size_t)NNODES * HIDTOT];
__device__ float g_h2[(size_t)NNODES * NCLS];
__device__ float g_als2[NNODES];
__device__ float g_ald2[NNODES];

// ---------------- CSR construction ----------------------------------------
__global__ void k_zero(int n) {
    int i = blockIdx.x * blockDim.x + threadIdx.x;
    if (i < n) { g_count[i] = 0; g_cursor[i] = 0; }
}

// Detect int64 vs int32 storage of edge_index and emit src/dst (+self loops),
// accumulating the per-destination histogram.
__global__ void k_convert(const void* __restrict__ edges, int E, int n) {
    __shared__ int s_is64;
    if (threadIdx.x == 0) {
        const long long* q = (const long long*)edges;
        int ok = 1;
#pragma unroll
        for (int t = 0; t < 16; t++) {
            long long v = q[t];
            if (v < 0 || v >= (long long)n) ok = 0;
        }
        s_is64 = ok;
    }
    __syncthreads();
    int i = blockIdx.x * blockDim.x + threadIdx.x;
    int Et = E + n;
    if (i >= Et) return;
    int s, d;
    if (i < E) {
        if (s_is64) {
            const long long* q = (const long long*)edges;
            s = (int)q[i];
            d = (int)q[(long long)E + i];
        } else {
            const int* q = (const int*)edges;
            s = q[i];
            d = q[E + i];
        }
    } else {
        s = i - E; d = i - E;   // self loop
    }
    g_src[i] = s;
    g_dst[i] = d;
    atomicAdd(&g_count[d], 1);
}

__global__ void k_scan_local(int n) {
    __shared__ int sh[1024];
    int i = blockIdx.x * 1024 + threadIdx.x;
    int v = (i < n) ? g_count[i] : 0;
    sh[threadIdx.x] = v;
    __syncthreads();
    for (int off = 1; off < 1024; off <<= 1) {
        int t = (threadIdx.x >= off) ? sh[threadIdx.x - off] : 0;
        __syncthreads();
        sh[threadIdx.x] += t;
        __syncthreads();
    }
    if (i < n) g_off[i] = sh[threadIdx.x] - v;           // exclusive
    if (threadIdx.x == 1023) g_bsum[blockIdx.x] = sh[1023];
}

__global__ void k_scan_sums(int nb) {
    __shared__ int sh[64];
    int v = (threadIdx.x < nb) ? g_bsum[threadIdx.x] : 0;
    sh[threadIdx.x] = v;
    __syncthreads();
    for (int off = 1; off < 64; off <<= 1) {
        int t = (threadIdx.x >= off) ? sh[threadIdx.x - off] : 0;
        __syncthreads();
        sh[threadIdx.x] += t;
        __syncthreads();
    }
    g_boff[threadIdx.x] = sh[threadIdx.x] - v;
}

__global__ void k_scan_add(int n, int Et) {
    int i = blockIdx.x * 1024 + threadIdx.x;
    if (i < n) g_off[i] += g_boff[blockIdx.x];
    if (i == 0) g_off[n] = Et;
}

__global__ void k_scatter(int Et) {
    int i = blockIdx.x * blockDim.x + threadIdx.x;
    if (i >= Et) return;
    int d = g_dst[i];
    int pos = g_off[d] + atomicAdd(&g_cursor[d], 1);
    g_csr[pos] = g_src[i];
}

// ---------------- GEMM1: h1 = x @ W1  (M x 256 x 256) ----------------------
// 128x64 tile, TK=16, 256 threads, 8x4 micro-tile per thread.
__global__ void k_gemm1(const float* __restrict__ X, const float* __restrict__ W, int M) {
    const int K = FIN, N = HIDTOT;
    __shared__ float  As[16][130];       // padded: conflict-free staging stores
    __shared__ float4 Bs[16][16];
    int tid = threadIdx.x;
    int row0 = blockIdx.y * 128;
    int col0 = blockIdx.x * 64;
    int tn = tid & 15, tm = tid >> 4;

    float acc[8][4];
#pragma unroll
    for (int j = 0; j < 8; j++)
#pragma unroll
        for (int c = 0; c < 4; c++) acc[j][c] = 0.f;

    const float4* X4 = (const float4*)X;
    const float4* W4 = (const float4*)W;

    for (int k0 = 0; k0 < K; k0 += 16) {
        // A tile: 128 rows x 16 k, 2 float4 per thread
#pragma unroll
        for (int r = 0; r < 2; r++) {
            int f = tid + r * 256;
            int m = f >> 2, kq = f & 3;
            int row = row0 + m;
            float4 v = make_float4(0.f, 0.f, 0.f, 0.f);
            if (row < M) v = X4[(size_t)row * (K / 4) + (k0 >> 2) + kq];
            As[kq * 4 + 0][m] = v.x;
            As[kq * 4 + 1][m] = v.y;
            As[kq * 4 + 2][m] = v.z;
            As[kq * 4 + 3][m] = v.w;
        }
        // B tile: 16 k x 64 n, 1 float4 per thread
        {
            int k = tid >> 4, nq = tid & 15;
            Bs[k][nq] = W4[(size_t)(k0 + k) * (N / 4) + (col0 >> 2) + nq];
        }
        __syncthreads();
#pragma unroll
        for (int k = 0; k < 16; k++) {
            float4 b = Bs[k][tn];
            float a[8];
#pragma unroll
            for (int j = 0; j < 8; j++) a[j] = As[k][tm * 8 + j];
#pragma unroll
            for (int j = 0; j < 8; j++) {
                acc[j][0] += a[j] * b.x;
                acc[j][1] += a[j] * b.y;
                acc[j][2] += a[j] * b.z;
                acc[j][3] += a[j] * b.w;
            }
        }
        __syncthreads();
    }
#pragma unroll
    for (int j = 0; j < 8; j++) {
        int row = row0 + tm * 8 + j;
        if (row < M) {
            float4 o = make_float4(acc[j][0], acc[j][1], acc[j][2], acc[j][3]);
            ((float4*)g_h1)[(size_t)row * (N / 4) + (col0 >> 2) + tn] = o;
        }
    }
}

// ---------------- attention logit dot products (layer 1) -------------------
__global__ void k_al1(const float* __restrict__ a_src, const float* __restrict__ a_dst, int M) {
    int w = (blockIdx.x * blockDim.x + threadIdx.x) >> 5;
    int lane = threadIdx.x & 31;
    if (w >= M) return;
    const float4* hp = (const float4*)(g_h1 + (size_t)w * HIDTOT);
    float4 v0 = hp[lane * 2], v1 = hp[lane * 2 + 1];
    const float4* as4 = (const float4*)a_src;
    const float4* ad4 = (const float4*)a_dst;
    float4 a0 = as4[lane * 2], a1 = as4[lane * 2 + 1];
    float4 d0 = ad4[lane * 2], d1 = ad4[lane * 2 + 1];
    float ps = v0.x * a0.x + v0.y * a0.y + v0.z * a0.z + v0.w * a0.w
             + v1.x * a1.x + v1.y * a1.y + v1.z * a1.z + v1.w * a1.w;
    float pd = v0.x * d0.x + v0.y * d0.y + v0.z * d0.z + v0.w * d0.w
             + v1.x * d1.x + v1.y * d1.y + v1.z * d1.z + v1.w * d1.w;
#pragma unroll
    for (int o = 4; o >= 1; o >>= 1) {
        ps += __shfl_down_sync(0xffffffffu, ps, o);
        pd += __shfl_down_sync(0xffffffffu, pd, o);
    }
    if ((lane & 7) == 0) {
        g_als1[w * NHEADS + (lane >> 3)] = ps;
        g_ald1[w * NHEADS + (lane >> 3)] = pd;
    }
}

// ---------------- layer-1 aggregation: online softmax, warp per node -------
// lane l owns absolute channels [l*8, l*8+8), head = l>>3. Epilogue: +b1, ELU.
__global__ void k_agg1(const float* __restrict__ b1, int M) {
    int w = (blockIdx.x * blockDim.x + threadIdx.x) >> 5;
    int lane = threadIdx.x & 31;
    if (w >= M) return;
    int h = lane >> 3;
    float ald = g_ald1[w * NHEADS + h];
    int beg = g_off[w], end = g_off[w + 1];
    float m = -1e30f, s = 0.f;
    float acc[8];
#pragma unroll
    for (int j = 0; j < 8; j++) acc[j] = 0.f;

    for (int idx = beg; idx < end; ++idx) {
        int src = g_csr[idx];
        float e = g_als1[src * NHEADS + h] + ald;
        e = (e > 0.f) ? e : 0.2f * e;
        float mn = fmaxf(m, e);
        float sc = __expf(m - mn);
        float p  = __expf(e - mn);
        const float4* hp = (const float4*)(g_h1 + (size_t)src * HIDTOT);
        float4 v0 = hp[lane * 2], v1 = hp[lane * 2 + 1];
        s = s * sc + p;
        acc[0] = acc[0] * sc + p * v0.x;
        acc[1] = acc[1] * sc + p * v0.y;
        acc[2] = acc[2] * sc + p * v0.z;
        acc[3] = acc[3] * sc + p * v0.w;
        acc[4] = acc[4] * sc + p * v1.x;
        acc[5] = acc[5] * sc + p * v1.y;
        acc[6] = acc[6] * sc + p * v1.z;
        acc[7] = acc[7] * sc + p * v1.w;
        m = mn;
    }
    float inv = 1.f / s;
#pragma unroll
    for (int j = 0; j < 8; j++) {
        float v = acc[j] * inv + b1[lane * 8 + j];
        v = (v > 0.f) ? v : (__expf(v) - 1.f);          // ELU
        g_h2in[(size_t)w * HIDTOT + lane * 8 + j] = v;
    }
}

// ---------------- GEMM2: h2 = h2in @ W2  (M x 256 x 32) --------------------
__global__ void k_gemm2(const float* __restrict__ W2, int M) {
    const int K = HIDTOT, N = NCLS;
    __shared__ float As[16][130];
    __shared__ float Bs[16][32];
    int tid = threadIdx.x;
    int row0 = blockIdx.x * 128;
    int tn = tid & 15, tm = tid >> 4;
    float acc[8][2];
#pragma unroll
    for (int j = 0; j < 8; j++) { acc[j][0] = 0.f; acc[j][1] = 0.f; }

    const float4* A4 = (const float4*)g_h2in;
    const float4* W4 = (const float4*)W2;

    for (int k0 = 0; k0 < K; k0 += 16) {
#pragma unroll
        for (int r = 0; r < 2; r++) {
            int f = tid + r * 256;
            int m = f >> 2, kq = f & 3;
            int row = row0 + m;
            float4 v = make_float4(0.f, 0.f, 0.f, 0.f);
            if (row < M) v = A4[(size_t)row * (K / 4) + (k0 >> 2) + kq];
            As[kq * 4 + 0][m] = v.x;
            As[kq * 4 + 1][m] = v.y;
            As[kq * 4 + 2][m] = v.z;
            As[kq * 4 + 3][m] = v.w;
        }
        if (tid < 128) {
            int k = tid >> 3, nq = tid & 7;
            float4 v = W4[(size_t)(k0 + k) * (N / 4) + nq];
            Bs[k][nq * 4 + 0] = v.x;
            Bs[k][nq * 4 + 1] = v.y;
            Bs[k][nq * 4 + 2] = v.z;
            Bs[k][nq * 4 + 3] = v.w;
        }
        __syncthreads();
#pragma unroll
        for (int k = 0; k < 16; k++) {
            float b0 = Bs[k][tn * 2], b1v = Bs[k][tn * 2 + 1];
#pragma unroll
            for (int j = 0; j < 8; j++) {
                float a = As[k][tm * 8 + j];
                acc[j][0] += a * b0;
                acc[j][1] += a * b1v;
            }
        }
        __syncthreads();
    }
#pragma unroll
    for (int j = 0; j < 8; j++) {
        int row = row0 + tm * 8 + j;
        if (row < M)
            ((float2*)g_h2)[(size_t)row * (N / 2) + tn] = make_float2(acc[j][0], acc[j][1]);
    }
}

__global__ void k_al2(const float* __restrict__ a_src, const float* __restrict__ a_dst, int M) {
    int w = (blockIdx.x * blockDim.x + threadIdx.x) >> 5;
    int lane = threadIdx.x & 31;
    if (w >= M) return;
    float v = g_h2[(size_t)w * NCLS + lane];
    float ps = v * a_src[lane];
    float pd = v * a_dst[lane];
#pragma unroll
    for (int o = 16; o >= 1; o >>= 1) {
        ps += __shfl_xor_sync(0xffffffffu, ps, o);
        pd += __shfl_xor_sync(0xffffffffu, pd, o);
    }
    if (lane == 0) { g_als2[w] = ps; g_ald2[w] = pd; }
}

// ---------------- layer-2 aggregation + log_softmax, warp per node ---------
__global__ void k_agg2(const float* __restrict__ b2, float* __restrict__ out, int M) {
    int w = (blockIdx.x * blockDim.x + threadIdx.x) >> 5;
    int lane = threadIdx.x & 31;
    if (w >= M) return;
    float ald = g_ald2[w];
    int beg = g_off[w], end = g_off[w + 1];
    float m = -1e30f, s = 0.f, acc = 0.f;
    for (int idx = beg; idx < end; ++idx) {
        int src = g_csr[idx];
        float e = g_als2[src] + ald;
        e = (e > 0.f) ? e : 0.2f * e;
        float mn = fmaxf(m, e);
        float sc = __expf(m - mn);
        float p  = __expf(e - mn);
        float hv = g_h2[(size_t)src * NCLS + lane];
        s = s * sc + p;
        acc = acc * sc + p * hv;
        m = mn;
    }
    float v = acc / s + b2[lane];
    // log_softmax over 32 lanes
    float mx = v;
#pragma unroll
    for (int o = 16; o >= 1; o >>= 1) mx = fmaxf(mx, __shfl_xor_sync(0xffffffffu, mx, o));
    float ex = __expf(v - mx);
    float sum = ex;
#pragma unroll
    for (int o = 16; o >= 1; o >>= 1) sum += __shfl_xor_sync(0xffffffffu, sum, o);
    out[(size_t)w * NCLS + lane] = v - mx - logf(sum);
}

// ---------------- launch ----------------------------------------------------
extern "C" void kernel_launch(void* const* d_in, const int* in_sizes, int n_in,
                              void* d_out, int out_size) {
    const float* x   = (const float*)d_in[0];
    const void*  ei  = d_in[1];
    const float* W1  = (const float*)d_in[2];
    const float* as1 = (const float*)d_in[3];
    const float* ad1 = (const float*)d_in[4];
    const float* b1  = (const float*)d_in[5];
    const float* W2  = (const float*)d_in[6];
    const float* as2 = (const float*)d_in[7];
    const float* ad2 = (const float*)d_in[8];
    const float* b2  = (const float*)d_in[9];
    float* out = (float*)d_out;

    int M  = in_sizes[0] / FIN;       // 50000
    int E  = in_sizes[1] / 2;         // 800000 (element count is dtype-agnostic)
    int Et = E + M;

    // CSR by destination
    k_zero<<<(M + 255) / 256, 256>>>(M);
    k_convert<<<(Et + 255) / 256, 256>>>(ei, E, M);
    int nb = (M + 1023) / 1024;
    k_scan_local<<<nb, 1024>>>(M);
    k_scan_sums<<<1, 64>>>(nb);
    k_scan_add<<<nb, 1024>>>(M, Et);
    k_scatter<<<(Et + 255) / 256, 256>>>(Et);

    // Layer 1
    dim3 g1(HIDTOT / 64, (M + 127) / 128);
    k_gemm1<<<g1, 256>>>(x, W1, M);
    k_al1<<<(M + 7) / 8, 256>>>(as1, ad1, M);
    k_agg1<<<(M + 7) / 8, 256>>>(b1, M);

    // Layer 2
    k_gemm2<<<(M + 127) / 128, 256>>>(W2, M);
    k_al2<<<(M + 7) / 8, 256>>>(as2, ad2, M);
    k_agg2<<<(M + 7) / 8, 256>>>(b2, out, M);
}